// round 6
// baseline (speedup 1.0000x reference)
#include <cuda_runtime.h>
#include <cstdint>

// DQ_Add_LayerNorm_Q : fused dequant + residual add + LayerNorm + int8 requant
// rows = 16384, dim = 4096.
// R6: persistent CTAs + 2-stage cp.async (LDGSTS) smem pipeline. Next row's
// 32KB streams into smem while the current row's reduction/epilogue runs —
// the R3 pipeline idea without its register cost (in-flight data lives in smem).

constexpr int TOKENS = 16384;
constexpr int DIM = 4096;
constexpr float EPS = 1e-5f;
constexpr float INPUT_SCALE = 0.01f;

constexpr int THREADS = 256;
constexpr int VEC = 4;
constexpr int ITER = DIM / (THREADS * VEC);        // 4
constexpr int NWARP = THREADS / 32;
constexpr int GRID = 152 * 3;                      // 152 SMs x 3 CTAs, one wave

constexpr int ROW_F_BYTES = DIM * 4;               // 16 KB
constexpr int STAGE_BYTES = 2 * ROW_F_BYTES;       // resid + qin = 32 KB
constexpr int SMEM_DYN    = 2 * STAGE_BYTES;       // 2 stages = 64 KB

__device__ __forceinline__ uint32_t smem_u32(const void* p) {
    return (uint32_t)__cvta_generic_to_shared(p);
}
__device__ __forceinline__ void cp_async16(uint32_t s, const void* g) {
    asm volatile("cp.async.cg.shared.global [%0], [%1], 16;" :: "r"(s), "l"(g));
}
__device__ __forceinline__ void cp_commit() {
    asm volatile("cp.async.commit_group;");
}
template <int N>
__device__ __forceinline__ void cp_wait() {
    asm volatile("cp.async.wait_group %0;" :: "n"(N));
}

__device__ __forceinline__ float warp_sum(float v) {
#pragma unroll
    for (int off = 16; off > 0; off >>= 1)
        v += __shfl_xor_sync(0xFFFFFFFFu, v, off);
    return v;
}

template <bool Q_AS_FLOAT>
__global__ __launch_bounds__(THREADS, 3)
void fused_dq_ln_q_kernel(const float* __restrict__ resid,
                          const int*   __restrict__ qin,
                          const float* __restrict__ weight,
                          const float* __restrict__ bias,
                          float* __restrict__ xout,
                          void*  __restrict__ qout)
{
    extern __shared__ char smem[];
    __shared__ float sh_s[2][NWARP], sh_ss[2][NWARP];

    const int tid  = threadIdx.x;
    const int lane = tid & 31, wid = tid >> 5;
    const int stride = gridDim.x;

    // per-stage smem base addresses (u32 shared-space)
    const uint32_t st_base = smem_u32(smem);

    auto issue_row = [&](int r, int buf) {
        const size_t base = (size_t)r * DIM;
        const float4* rg = reinterpret_cast<const float4*>(resid + base);
        const int4*   qg = reinterpret_cast<const int4*>(qin + base);
        const uint32_t s_res = st_base + buf * STAGE_BYTES;
        const uint32_t s_qin = s_res + ROW_F_BYTES;
#pragma unroll
        for (int i = 0; i < ITER; i++) {
            const int idx = tid + i * THREADS;
            cp_async16(s_res + idx * 16, &rg[idx]);
            cp_async16(s_qin + idx * 16, &qg[idx]);
        }
        cp_commit();
    };

    int row = blockIdx.x;
    if (row < TOKENS) issue_row(row, 0);

    int buf = 0;
    while (row < TOKENS) {
        const int next = row + stride;
        const bool has_next = next < TOKENS;
        if (has_next) issue_row(next, buf ^ 1);

        // wait for current stage (next stays in flight)
        if (has_next) cp_wait<1>(); else cp_wait<0>();

        // consume: each thread reads exactly the words it copied itself
        const float4* rs = reinterpret_cast<const float4*>(smem + buf * STAGE_BYTES);
        const int4*   qs = reinterpret_cast<const int4*>(smem + buf * STAGE_BYTES + ROW_F_BYTES);

        float4 xv[ITER];
        float s = 0.0f, ss = 0.0f;
#pragma unroll
        for (int i = 0; i < ITER; i++) {
            const int idx = tid + i * THREADS;
            float4 r = rs[idx];
            int4   q = qs[idx];
            float4 v;
            v.x = fmaf((float)q.x, INPUT_SCALE, r.x);
            v.y = fmaf((float)q.y, INPUT_SCALE, r.y);
            v.z = fmaf((float)q.z, INPUT_SCALE, r.z);
            v.w = fmaf((float)q.w, INPUT_SCALE, r.w);
            xv[i] = v;
            s  += (v.x + v.y) + (v.z + v.w);
            ss += fmaf(v.x, v.x, v.y * v.y) + fmaf(v.z, v.z, v.w * v.w);
        }

        const size_t base = (size_t)row * DIM;
        float4* xo4 = reinterpret_cast<float4*>(xout + base);
#pragma unroll
        for (int i = 0; i < ITER; i++)
            __stcs(&xo4[tid + i * THREADS], xv[i]);

        // block reduction (two barriers; first one is also the WAR guard
        // for stage-buffer reuse: all smem-stage reads precede it)
        float ws  = warp_sum(s);
        float wss = warp_sum(ss);
        if (lane == 0) { sh_s[buf][wid] = ws; sh_ss[buf][wid] = wss; }
        __syncthreads();
        if (wid == 0) {
            float a = (lane < NWARP) ? sh_s[buf][lane]  : 0.0f;
            float b = (lane < NWARP) ? sh_ss[buf][lane] : 0.0f;
#pragma unroll
            for (int off = NWARP / 2; off > 0; off >>= 1) {
                a += __shfl_xor_sync(0xFFFFFFFFu, a, off);
                b += __shfl_xor_sync(0xFFFFFFFFu, b, off);
            }
            if (lane == 0) { sh_s[buf][0] = a; sh_ss[buf][0] = b; }
        }
        __syncthreads();
        const float ts = sh_s[buf][0], tss = sh_ss[buf][0];

        const float mean = ts * (1.0f / DIM);
        const float var  = fmaf(-mean, mean, tss * (1.0f / DIM));
        const float inv  = rsqrtf(var + EPS);

        const float4* w4 = reinterpret_cast<const float4*>(weight);
        const float4* b4 = reinterpret_cast<const float4*>(bias);
#pragma unroll
        for (int i = 0; i < ITER; i++) {
            const int idx = tid + i * THREADS;
            float4 w  = __ldg(&w4[idx]);   // L1-hot across persistent rows
            float4 bb = __ldg(&b4[idx]);
            float4 v = xv[i];
            float lx = fmaf((v.x - mean) * inv, w.x, bb.x);
            float ly = fmaf((v.y - mean) * inv, w.y, bb.y);
            float lz = fmaf((v.z - mean) * inv, w.z, bb.z);
            float lw = fmaf((v.w - mean) * inv, w.w, bb.w);
            // jnp.round = round-half-to-even -> rintf, then clip
            float qx = fminf(fmaxf(rintf(lx), -128.0f), 127.0f);
            float qy = fminf(fmaxf(rintf(ly), -128.0f), 127.0f);
            float qz = fminf(fmaxf(rintf(lz), -128.0f), 127.0f);
            float qw = fminf(fmaxf(rintf(lw), -128.0f), 127.0f);
            if (Q_AS_FLOAT) {
                float4* qo = reinterpret_cast<float4*>((float*)qout + base);
                __stcs(&qo[idx], make_float4(qx, qy, qz, qw));
            } else {
                char4* qo = reinterpret_cast<char4*>((int8_t*)qout + base);
                char4 c;
                c.x = (signed char)(int)qx;
                c.y = (signed char)(int)qy;
                c.z = (signed char)(int)qz;
                c.w = (signed char)(int)qw;
                qo[idx] = c;
            }
        }

        row = next;
        buf ^= 1;
    }
}

extern "C" void kernel_launch(void* const* d_in, const int* in_sizes, int n_in,
                              void* d_out, int out_size) {
    const float* resid  = (const float*)d_in[0];
    const int*   qin    = (const int*)d_in[1];
    const float* weight = (const float*)d_in[2];
    const float* bias   = (const float*)d_in[3];

    const size_t N = (size_t)TOKENS * DIM;
    float* xout = (float*)d_out;

    if ((size_t)out_size == 2 * N) {
        cudaFuncSetAttribute(fused_dq_ln_q_kernel<true>,
                             cudaFuncAttributeMaxDynamicSharedMemorySize, SMEM_DYN);
        void* qout = (void*)(xout + N);
        fused_dq_ln_q_kernel<true><<<GRID, THREADS, SMEM_DYN>>>(resid, qin, weight, bias, xout, qout);
    } else {
        cudaFuncSetAttribute(fused_dq_ln_q_kernel<false>,
                             cudaFuncAttributeMaxDynamicSharedMemorySize, SMEM_DYN);
        void* qout = (void*)((int8_t*)d_out + N * sizeof(float));
        fused_dq_ln_q_kernel<false><<<GRID, THREADS, SMEM_DYN>>>(resid, qin, weight, bias, xout, qout);
    }
}

// round 8
// speedup vs baseline: 1.1418x; 1.1418x over previous
#include <cuda_runtime.h>
#include <cstdint>

// DQ_Add_LayerNorm_Q : fused dequant + residual add + LayerNorm + int8 requant
// rows = 16384, dim = 4096. One block per row, single DRAM pass.
// R7 = R2 structure (best: 156.7us) with lower peak register pressure:
// resid loads land directly in xv, qin fma'd in place -> peak payload 32 regs,
// letting occupancy rise 4 -> 5 at unchanged per-thread MLP of 8.

constexpr int TOKENS = 16384;
constexpr int DIM = 4096;
constexpr float EPS = 1e-5f;
constexpr float INPUT_SCALE = 0.01f;

constexpr int THREADS = 256;
constexpr int VEC = 4;                              // float4 / int4
constexpr int ITER = DIM / (THREADS * VEC);         // 4 iterations per thread
constexpr int NWARP = THREADS / 32;

__device__ __forceinline__ float warp_sum(float v) {
#pragma unroll
    for (int off = 16; off > 0; off >>= 1)
        v += __shfl_xor_sync(0xFFFFFFFFu, v, off);
    return v;
}

template <bool Q_AS_FLOAT>
__global__ __launch_bounds__(THREADS, 5)
void fused_dq_ln_q_kernel(const float* __restrict__ resid,
                          const int*   __restrict__ qin,
                          const float* __restrict__ weight,
                          const float* __restrict__ bias,
                          float* __restrict__ xout,
                          void*  __restrict__ qout)
{
    const int row = blockIdx.x;
    const int tid = threadIdx.x;
    const size_t base = (size_t)row * DIM;

    const float4* r4 = reinterpret_cast<const float4*>(resid + base);
    const int4*   q4 = reinterpret_cast<const int4*>(qin + base);

    // Front-batch all 8 independent 128-bit loads; resid lands directly in xv.
    float4 xv[ITER];
    int4   qv[ITER];
#pragma unroll
    for (int i = 0; i < ITER; i++) {
        const int idx = tid + i * THREADS;
        xv[i] = __ldcs(&r4[idx]);   // streaming: no reuse
        qv[i] = __ldcs(&q4[idx]);
    }

    float s = 0.0f, ss = 0.0f;
#pragma unroll
    for (int i = 0; i < ITER; i++) {
        // dequant + add, in place (qv dies here -> lower peak live regs)
        xv[i].x = fmaf((float)qv[i].x, INPUT_SCALE, xv[i].x);
        xv[i].y = fmaf((float)qv[i].y, INPUT_SCALE, xv[i].y);
        xv[i].z = fmaf((float)qv[i].z, INPUT_SCALE, xv[i].z);
        xv[i].w = fmaf((float)qv[i].w, INPUT_SCALE, xv[i].w);
        s  += (xv[i].x + xv[i].y) + (xv[i].z + xv[i].w);
        ss += fmaf(xv[i].x, xv[i].x, xv[i].y * xv[i].y)
            + fmaf(xv[i].z, xv[i].z, xv[i].w * xv[i].w);
    }

    // Write updated residual x immediately (fire-and-forget, overlaps reduction).
    float4* xo4 = reinterpret_cast<float4*>(xout + base);
#pragma unroll
    for (int i = 0; i < ITER; i++)
        __stcs(&xo4[tid + i * THREADS], xv[i]);

    // block reduction of s, ss
    __shared__ float sh_s[NWARP], sh_ss[NWARP];
    float ws  = warp_sum(s);
    float wss = warp_sum(ss);
    const int lane = tid & 31, wid = tid >> 5;
    if (lane == 0) { sh_s[wid] = ws; sh_ss[wid] = wss; }
    __syncthreads();
    if (wid == 0) {
        float a = (lane < NWARP) ? sh_s[lane]  : 0.0f;
        float b = (lane < NWARP) ? sh_ss[lane] : 0.0f;
#pragma unroll
        for (int off = NWARP / 2; off > 0; off >>= 1) {
            a += __shfl_xor_sync(0xFFFFFFFFu, a, off);
            b += __shfl_xor_sync(0xFFFFFFFFu, b, off);
        }
        if (lane == 0) { sh_s[0] = a; sh_ss[0] = b; }
    }
    __syncthreads();
    const float ts = sh_s[0], tss = sh_ss[0];

    const float mean = ts * (1.0f / DIM);
    const float var  = fmaf(-mean, mean, tss * (1.0f / DIM));
    const float inv  = rsqrtf(var + EPS);

    // affine + quantize
    const float4* w4 = reinterpret_cast<const float4*>(weight);
    const float4* b4 = reinterpret_cast<const float4*>(bias);
#pragma unroll
    for (int i = 0; i < ITER; i++) {
        const int idx = tid + i * THREADS;
        float4 w  = __ldg(&w4[idx]);   // reused across all rows: keep cached
        float4 bb = __ldg(&b4[idx]);
        float4 v = xv[i];
        float lx = fmaf((v.x - mean) * inv, w.x, bb.x);
        float ly = fmaf((v.y - mean) * inv, w.y, bb.y);
        float lz = fmaf((v.z - mean) * inv, w.z, bb.z);
        float lw = fmaf((v.w - mean) * inv, w.w, bb.w);
        // jnp.round = round-half-to-even -> rintf, then clip
        float qx = fminf(fmaxf(rintf(lx), -128.0f), 127.0f);
        float qy = fminf(fmaxf(rintf(ly), -128.0f), 127.0f);
        float qz = fminf(fmaxf(rintf(lz), -128.0f), 127.0f);
        float qw = fminf(fmaxf(rintf(lw), -128.0f), 127.0f);
        if (Q_AS_FLOAT) {
            float4* qo = reinterpret_cast<float4*>((float*)qout + base);
            __stcs(&qo[idx], make_float4(qx, qy, qz, qw));
        } else {
            char4* qo = reinterpret_cast<char4*>((int8_t*)qout + base);
            char4 c;
            c.x = (signed char)(int)qx;
            c.y = (signed char)(int)qy;
            c.z = (signed char)(int)qz;
            c.w = (signed char)(int)qw;
            qo[idx] = c;
        }
    }
}

extern "C" void kernel_launch(void* const* d_in, const int* in_sizes, int n_in,
                              void* d_out, int out_size) {
    const float* resid  = (const float*)d_in[0];
    const int*   qin    = (const int*)d_in[1];
    const float* weight = (const float*)d_in[2];
    const float* bias   = (const float*)d_in[3];

    const size_t N = (size_t)TOKENS * DIM;
    float* xout = (float*)d_out;

    if ((size_t)out_size == 2 * N) {
        // outputs concatenated as float32: [x fp32 | q cast to fp32]
        void* qout = (void*)(xout + N);
        fused_dq_ln_q_kernel<true><<<TOKENS, THREADS>>>(resid, qin, weight, bias, xout, qout);
    } else {
        // byte layout: [x fp32 bytes | q int8 bytes]
        void* qout = (void*)((int8_t*)d_out + N * sizeof(float));
        fused_dq_ln_q_kernel<false><<<TOKENS, THREADS>>>(resid, qin, weight, bias, xout, qout);
    }
}